// round 10
// baseline (speedup 1.0000x reference)
#include <cuda_runtime.h>
#include <cstdint>

#define CRF_B 256
#define CRF_T 512
#define CRF_L 64

typedef unsigned long long ull;

// ---- packed f32x2 helpers (Blackwell dual-FP32) ----
__device__ __forceinline__ ull pack2(float lo, float hi) {
    ull r; asm("mov.b64 %0, {%1, %2};" : "=l"(r) : "f"(lo), "f"(hi)); return r;
}
__device__ __forceinline__ void unpack2(ull v, float& lo, float& hi) {
    asm("mov.b64 {%0, %1}, %2;" : "=f"(lo), "=f"(hi) : "l"(v));
}
__device__ __forceinline__ ull fma2(ull a, ull b, ull c) {
    ull d; asm("fma.rn.f32x2 %0, %1, %2, %3;" : "=l"(d) : "l"(a), "l"(b), "l"(c)); return d;
}
__device__ __forceinline__ ull add2(ull a, ull b) {
    ull d; asm("add.rn.f32x2 %0, %1, %2;" : "=l"(d) : "l"(a), "l"(b)); return d;
}

// 128 CTAs (1/SM), 2 batch rows per CTA, 8 warps:
//   wid 0: fwd row0 (SMSP0)  wid 1: bwd row0 (SMSP1)
//   wid 2: fwd row1 (SMSP2)  wid 3: bwd row1 (SMSP3)
//   wid 4-7: scores (one per SMSP).
// Buffer convention: state of time t lives in buffer t&1.
// Interleaved state: lane l owns labels (2l, 2l+1); buffer in natural label
// order via STS.64 write + 16x LDS.128 broadcast read, __syncwarp per step.
// Renorm every 4 steps by an EXACT power-of-2 scale from stale w[0]'s
// exponent (ALU-only: no rcp, no logf). Emissions: 4-deep register ring,
// one LDG.64 with immediate offset per step, pointer bumped per 4-group.
__global__ __launch_bounds__(256, 1)
void CRF_48266842472844_kernel(const float* __restrict__ y_true,
                               const float* __restrict__ y_pred,
                               const float* __restrict__ trans,
                               float* __restrict__ out) {
    const int tid  = threadIdx.x;
    const int lane = tid & 31;
    const int wid  = tid >> 5;

    __shared__ __align__(16) float qf[2][2][CRF_L];   // [row][buf][label] fwd
    __shared__ __align__(16) float qb[2][2][CRF_L];   // [row][buf][label] bwd
    __shared__ __align__(16) float2 bout2[2][32];     // beta_255 pairs
    __shared__ int   labs[2][CRF_T];
    __shared__ float sMb[2], sP[2][2], sTs[2][2];

    float vA = 0.0f, vB = 0.0f, M = 0.0f;   // live across final barrier

// One matvec step. qread: 64 floats natural order; writes pair (2l,2l+1).
// CONSUME: exact power-of-2 renorm from stale w[0] exponent (ALU only).
#define CORE(qread, qwrite, EA, EB, eX, eY, CONSUME) do {                     \
    float gA = __expf(eX), gB = __expf(eY);                                   \
    const ulonglong2* q2 = (const ulonglong2*)(qread);                        \
    ulonglong2 qv0 = q2[0];                                                   \
    if (CONSUME) {                                                            \
        float m0, mh; unpack2(qv0.x, m0, mh); (void)mh;                       \
        unsigned mb = __float_as_uint(m0);                                    \
        int ef = (int)(mb >> 23) - 127;                                       \
        float r = __uint_as_float((254u - (mb >> 23)) << 23);  /* 2^-ef */    \
        M = fmaf((float)ef, 0.69314718056f, M);                               \
        gA *= r; gB *= r;                                                     \
    }                                                                         \
    ull a0 = 0ull, a1 = 0ull, b0 = 0ull, b1 = 0ull;                           \
    _Pragma("unroll")                                                         \
    for (int k = 0; k < 16; k++) {                                            \
        ulonglong2 qv = (k == 0) ? qv0 : q2[k];                               \
        a0 = fma2(qv.x, EA[2 * k],     a0);                                   \
        b0 = fma2(qv.x, EB[2 * k],     b0);                                   \
        a1 = fma2(qv.y, EA[2 * k + 1], a1);                                   \
        b1 = fma2(qv.y, EB[2 * k + 1], b1);                                   \
    }                                                                         \
    a0 = add2(a0, a1); b0 = add2(b0, b1);                                     \
    { float lo, hi; unpack2(a0, lo, hi); vA = (lo + hi) * gA;                 \
      unpack2(b0, lo, hi); vB = (lo + hi) * gB; }                             \
    ((float2*)(qwrite))[lane] = make_float2(vA, vB);                          \
    __syncwarp();                                                             \
} while (0)

    if (wid < 4) {
        const int row  = wid >> 1;
        const int kind = wid & 1;           // 0 = fwd, 1 = bwd
        const int b    = 2 * blockIdx.x + row;
        const float2* yp2 = (const float2*)(y_pred + (size_t)b * CRF_T * CRF_L);
        ull Ea[32], Eb[32];
        float2 pe[4];                        // 4-deep ring, slot = t & 3

        if (kind == 0) {
            // ===== FORWARD alpha, t = 0..255. Outputs j0=2l, j1=2l+1.
            // Ea[k] = (E[2k][j0], E[2k+1][j0]); Eb[k] = same for j1.
#pragma unroll
            for (int k = 0; k < 32; k++) {
                float2 r0 = __ldg((const float2*)&trans[(2 * k)     * CRF_L + 2 * lane]);
                float2 r1 = __ldg((const float2*)&trans[(2 * k + 1) * CRF_L + 2 * lane]);
                Ea[k] = pack2(__expf(r0.x), __expf(r1.x));
                Eb[k] = pack2(__expf(r0.y), __expf(r1.y));
            }
            float2 e0 = yp2[lane];
            vA = __expf(e0.x); vB = __expf(e0.y);
            ((float2*)qf[row][0])[lane] = make_float2(vA, vB);   // alpha_0 -> buf 0
            pe[1] = yp2[1 * 32 + lane];      // t=1 -> slot 1
            pe[2] = yp2[2 * 32 + lane];      // t=2 -> slot 2
            pe[3] = yp2[3 * 32 + lane];      // t=3 -> slot 3
            pe[0] = yp2[4 * 32 + lane];      // t=4 -> slot 0
            const float2* pf = yp2 + 5 * 32 + lane;   // next prefetch target: t=5
            __syncwarp();

// consumes pe[t&3]; prefetches t+4 into the same slot from pf[OFF*32]
#define FSTEP(t_, OFF, CONSUME) do {                                          \
    float2 _e = pe[(t_) & 3];                                                 \
    pe[(t_) & 3] = pf[(OFF) * 32];                                            \
    CORE(qf[row][(t_ + 1) & 1], qf[row][(t_) & 1], Ea, Eb, _e.x, _e.y, CONSUME); \
} while (0)

            FSTEP(1, 0, false); FSTEP(2, 1, false); FSTEP(3, 2, false);
            pf += 3 * 32;                    // now at t=8 = first group's t4+4
#pragma unroll 1
            for (int g4 = 0; g4 < 63; g4++) {
                const int t4 = 4 * g4 + 4;
                FSTEP(t4 + 0, 0, true);
                FSTEP(t4 + 1, 1, false);
                FSTEP(t4 + 2, 2, false);
                FSTEP(t4 + 3, 3, false);
                pf += 4 * 32;
            }
#undef FSTEP
            // vA, vB = alpha~_255 pair ; M = Macc_f
        } else {
            // ===== BACKWARD u_t = g_t o (E u_{t+1}), t = 510..256.
            // Outputs i0=2l, i1=2l+1; Ea[k] = (E[i0][2k], E[i0][2k+1]).
#pragma unroll
            for (int m = 0; m < 16; m++) {
                float4 ra = __ldg((const float4*)&trans[(2 * lane)     * CRF_L + 4 * m]);
                Ea[2 * m]     = pack2(__expf(ra.x), __expf(ra.y));
                Ea[2 * m + 1] = pack2(__expf(ra.z), __expf(ra.w));
                float4 rb = __ldg((const float4*)&trans[(2 * lane + 1) * CRF_L + 4 * m]);
                Eb[2 * m]     = pack2(__expf(rb.x), __expf(rb.y));
                Eb[2 * m + 1] = pack2(__expf(rb.z), __expf(rb.w));
            }
            float2 e0 = yp2[511 * 32 + lane];
            vA = __expf(e0.x); vB = __expf(e0.y);   // u_511 = g_511
            ((float2*)qb[row][1])[lane] = make_float2(vA, vB);   // u_511 -> buf 1 (511&1)
            pe[2] = yp2[510 * 32 + lane];    // t=510 -> slot 2 (510&3)
            pe[1] = yp2[509 * 32 + lane];    // t=509 -> slot 1
            pe[0] = yp2[508 * 32 + lane];    // t=508 -> slot 0
            pe[3] = yp2[507 * 32 + lane];    // t=507 -> slot 3
            const float2* pf = yp2 + 506 * 32 + lane;  // next prefetch: t=506
            __syncwarp();

// consumes pe[t&3]; prefetches t-4 into the same slot from pf[-OFF*32]
#define BSTEP(t_, OFF, CONSUME) do {                                          \
    float2 _e = pe[(t_) & 3];                                                 \
    pe[(t_) & 3] = pf[-(OFF) * 32];                                           \
    CORE(qb[row][(t_ + 1) & 1], qb[row][(t_) & 1], Ea, Eb, _e.x, _e.y, CONSUME); \
} while (0)

            BSTEP(510, 0, false); BSTEP(509, 1, false); BSTEP(508, 2, false);
            pf -= 3 * 32;                    // now at t=503 = first group's tg-4
#pragma unroll 1
            for (int g4 = 0; g4 < 63; g4++) {
                const int tg = 507 - 4 * g4;
                BSTEP(tg - 0, 0, true);
                BSTEP(tg - 1, 1, false);
                BSTEP(tg - 2, 2, false);
                BSTEP(tg - 3, 3, false);
                pf -= 4 * 32;
            }
#undef BSTEP
            // final: beta_255 = E u_256 (renorm, no emission). u_256 in buf 0.
            {
                const ulonglong2* q2 = (const ulonglong2*)qb[row][0];
                ulonglong2 qv0 = q2[0];
                float m0, mh; unpack2(qv0.x, m0, mh); (void)mh;
                unsigned mb = __float_as_uint(m0);
                int ef = (int)(mb >> 23) - 127;
                float r = __uint_as_float((254u - (mb >> 23)) << 23);
                M = fmaf((float)ef, 0.69314718056f, M);
                ull a0 = 0ull, a1 = 0ull, b0 = 0ull, b1 = 0ull;
#pragma unroll
                for (int k = 0; k < 16; k++) {
                    ulonglong2 qv = (k == 0) ? qv0 : q2[k];
                    a0 = fma2(qv.x, Ea[2 * k],     a0);
                    b0 = fma2(qv.x, Eb[2 * k],     b0);
                    a1 = fma2(qv.y, Ea[2 * k + 1], a1);
                    b1 = fma2(qv.y, Eb[2 * k + 1], b1);
                }
                a0 = add2(a0, a1); b0 = add2(b0, b1);
                float lo, hi, oA, oB;
                unpack2(a0, lo, hi); oA = (lo + hi) * r;
                unpack2(b0, lo, hi); oB = (lo + hi) * r;
                bout2[row][lane] = make_float2(oA, oB);
            }
            if (lane == 0) sMb[row] = M;
        }
    } else {
        // ================= SCORES (wid 4-7) ==============================
        const int sw     = wid - 4;
        const int row    = sw >> 1;
        const int half_t = sw & 1;
        const int b      = 2 * blockIdx.x + row;
        const float* yp = y_pred + (size_t)b * CRF_T * CRF_L;
        const float* yt = y_true + (size_t)b * CRF_T * CRF_L;
        const float4* yp4 = (const float4*)yp;
        const float4* yt4 = (const float4*)yt;
        const int base = half_t * 256;
        const int hh = lane >> 4, l4 = lane & 15;

        float pacc = 0.0f;
#pragma unroll 4
        for (int t = base; t < base + 256; t += 2) {
            const int tt = t + hh;
            float4 p = yp4[tt * 16 + l4];
            float4 q = yt4[tt * 16 + l4];
            pacc += p.x * q.x + p.y * q.y + p.z * q.z + p.w * q.w;
            int c = -1;
            if      (q.x > 0.5f) c = 0;
            else if (q.y > 0.5f) c = 1;
            else if (q.z > 0.5f) c = 2;
            else if (q.w > 0.5f) c = 3;
            unsigned m  = __ballot_sync(0xffffffffu, c >= 0);
            unsigned mh = (m >> (hh * 16)) & 0xffffu;
            int src = hh * 16 + (__ffs(mh) - 1);
            int lab = __shfl_sync(0xffffffffu, 4 * l4 + c, src);
            if (l4 == 0) labs[row][tt] = lab;
        }
        asm volatile("bar.sync 1, 128;" ::: "memory");   // stitch labels

        float ts = 0.0f;
        const int tmax = half_t ? (CRF_T - 1) : 256;
#pragma unroll 4
        for (int t0 = base + lane; t0 < tmax; t0 += 32)
            ts += __ldg(&trans[labs[row][t0] * CRF_L + labs[row][t0 + 1]]);
#pragma unroll
        for (int s = 16; s > 0; s >>= 1) {
            pacc += __shfl_xor_sync(0xffffffffu, pacc, s);
            ts   += __shfl_xor_sync(0xffffffffu, ts, s);
        }
        if (lane == 0) { sP[row][half_t] = pacc; sTs[row][half_t] = ts; }
    }

    __syncthreads();

    // ================= COMBINE: fwd warps (wid 0, 2) =====================
    if (wid < 4 && (wid & 1) == 0) {
        const int row = wid >> 1;
        float2 bb = bout2[row][lane];
        float dot = vA * bb.x + vB * bb.y;
#pragma unroll
        for (int s = 16; s > 0; s >>= 1)
            dot += __shfl_xor_sync(0xffffffffu, dot, s);
        if (lane == 0) {
            float P  = sP[row][0] + sP[row][1];
            float TS = sTs[row][0] + sTs[row][1];
            out[2 * blockIdx.x + row] = (M + sMb[row] + logf(dot)) - P - TS;
        }
    }
#undef CORE
}

extern "C" void kernel_launch(void* const* d_in, const int* in_sizes, int n_in,
                              void* d_out, int out_size) {
    const float* y_true = (const float*)d_in[0];
    const float* y_pred = (const float*)d_in[1];
    const float* trans  = (const float*)d_in[2];
    float* out = (float*)d_out;
    (void)in_sizes; (void)n_in; (void)out_size;
    CRF_48266842472844_kernel<<<CRF_B / 2, 256>>>(y_true, y_pred, trans, out);
}

// round 11
// speedup vs baseline: 1.0926x; 1.0926x over previous
#include <cuda_runtime.h>
#include <cstdint>

#define CRF_B 256
#define CRF_T 512
#define CRF_L 64

typedef unsigned long long ull;

// ---- bf16x2 helpers ----
__device__ __forceinline__ unsigned bfma2(unsigned a, unsigned b, unsigned c) {
    unsigned d; asm("fma.rn.bf16x2 %0, %1, %2, %3;" : "=r"(d) : "r"(a), "r"(b), "r"(c)); return d;
}
// pack (lo, hi) floats -> bf16x2 (PTX: first source goes to the HIGH half)
__device__ __forceinline__ unsigned f2bf2(float lo, float hi) {
    unsigned d; asm("cvt.rn.bf16x2.f32 %0, %1, %2;" : "=r"(d) : "f"(hi), "f"(lo)); return d;
}
__device__ __forceinline__ float bf_lo(unsigned u) { return __uint_as_float(u << 16); }
__device__ __forceinline__ float bf_hi(unsigned u) { return __uint_as_float(u & 0xffff0000u); }

// 128 CTAs (1/SM), 2 batch rows per CTA, 8 warps:
//   wid 0: fwd row0 (SMSP0)  wid 1: bwd row0 (SMSP1)
//   wid 2: fwd row1 (SMSP2)  wid 3: bwd row1 (SMSP3)
//   wid 4-7: scores (one per SMSP).
// bf16 mainloop: state in smem as 64 bf16x2 words, each DUPLICATED (w_i,w_i)
// so the packed HFMA2 against E[i] = (E[i][j0], E[i][j1]) needs no swizzle.
// 64 HFMA2/step (rt=2 -> 128 issue cyc vs 192 for banked f32x2). Reduction
// tail in fp32 (bf16->fp32 = exact shift). Renorm every 4 steps by exact
// power-of-2 from stale w[0] bf16 exponent. Buffer of time t = buf t&1.
// __syncwarp per step is REQUIRED (independent thread scheduling).
__global__ __launch_bounds__(256, 1)
void CRF_48266842472844_kernel(const float* __restrict__ y_true,
                               const float* __restrict__ y_pred,
                               const float* __restrict__ trans,
                               float* __restrict__ out) {
    const int tid  = threadIdx.x;
    const int lane = tid & 31;
    const int wid  = tid >> 5;

    __shared__ __align__(16) unsigned qf[2][2][CRF_L];   // [row][buf][word] fwd
    __shared__ __align__(16) unsigned qb[2][2][CRF_L];   // [row][buf][word] bwd
    __shared__ __align__(16) float2 bout2[2][32];        // beta_255 pairs (fp32)
    __shared__ int   labs[2][CRF_T];
    __shared__ float sMb[2], sP[2][2], sTs[2][2];

    float vA = 0.0f, vB = 0.0f, M = 0.0f;   // live across final barrier

// One matvec step. qread: 64 duplicated bf16x2 words; lane writes words
// 2l (vA,vA) and 2l+1 (vB,vB) as one STS.64.
#define CORE(qread, qwrite, E, eX, eY, CONSUME) do {                          \
    float gA = __expf(eX), gB = __expf(eY);                                   \
    const uint4* q4 = (const uint4*)(qread);                                  \
    uint4 qv0 = q4[0];                                                        \
    if (CONSUME) {                                                            \
        unsigned eb = (qv0.x >> 7) & 0xffu;      /* bf16-lo exponent */       \
        float r = __uint_as_float((254u - eb) << 23);   /* 2^-ef exact */     \
        M = fmaf((float)((int)eb - 127), 0.69314718056f, M);                  \
        gA *= r; gB *= r;                                                     \
    }                                                                         \
    unsigned a0 = 0u, a1 = 0u, a2 = 0u, a3 = 0u;                              \
    _Pragma("unroll")                                                         \
    for (int m = 0; m < 16; m++) {                                            \
        uint4 qv = (m == 0) ? qv0 : q4[m];                                    \
        a0 = bfma2(qv.x, E[4 * m + 0], a0);                                   \
        a1 = bfma2(qv.y, E[4 * m + 1], a1);                                   \
        a2 = bfma2(qv.z, E[4 * m + 2], a2);                                   \
        a3 = bfma2(qv.w, E[4 * m + 3], a3);                                   \
    }                                                                         \
    float sA = (bf_lo(a0) + bf_lo(a1)) + (bf_lo(a2) + bf_lo(a3));             \
    float sB = (bf_hi(a0) + bf_hi(a1)) + (bf_hi(a2) + bf_hi(a3));             \
    vA = sA * gA; vB = sB * gB;                                               \
    ((uint2*)(qwrite))[lane] = make_uint2(f2bf2(vA, vA), f2bf2(vB, vB));      \
    __syncwarp();                                                             \
} while (0)

    if (wid < 4) {
        const int row  = wid >> 1;
        const int kind = wid & 1;           // 0 = fwd, 1 = bwd
        const int b    = 2 * blockIdx.x + row;
        const float2* yp2 = (const float2*)(y_pred + (size_t)b * CRF_T * CRF_L);
        unsigned E[64];                      // bf16x2 transition operands
        float2 pe[4];                        // 4-deep emission ring, slot = t & 3

        if (kind == 0) {
            // ===== FORWARD alpha, t = 0..255. Outputs j0=2l, j1=2l+1.
            // E[i] = bf16x2(exp(trans[i][j0]), exp(trans[i][j1])).
#pragma unroll
            for (int i = 0; i < 64; i++) {
                float2 r0 = __ldg((const float2*)&trans[i * CRF_L + 2 * lane]);
                E[i] = f2bf2(__expf(r0.x), __expf(r0.y));
            }
            float2 e0 = yp2[lane];
            vA = __expf(e0.x); vB = __expf(e0.y);
            ((uint2*)qf[row][0])[lane] = make_uint2(f2bf2(vA, vA), f2bf2(vB, vB)); // alpha_0 -> buf 0
            pe[1] = yp2[1 * 32 + lane];
            pe[2] = yp2[2 * 32 + lane];
            pe[3] = yp2[3 * 32 + lane];
            pe[0] = yp2[4 * 32 + lane];
            const float2* pf = yp2 + 5 * 32 + lane;   // next prefetch: t=5
            __syncwarp();

#define FSTEP(t_, OFF, CONSUME) do {                                          \
    float2 _e = pe[(t_) & 3];                                                 \
    pe[(t_) & 3] = pf[(OFF) * 32];                                            \
    CORE(qf[row][(t_ + 1) & 1], qf[row][(t_) & 1], E, _e.x, _e.y, CONSUME);   \
} while (0)

            FSTEP(1, 0, false); FSTEP(2, 1, false); FSTEP(3, 2, false);
            pf += 3 * 32;
#pragma unroll 1
            for (int g4 = 0; g4 < 63; g4++) {
                const int t4 = 4 * g4 + 4;
                FSTEP(t4 + 0, 0, true);
                FSTEP(t4 + 1, 1, false);
                FSTEP(t4 + 2, 2, false);
                FSTEP(t4 + 3, 3, false);
                pf += 4 * 32;
            }
#undef FSTEP
            // vA, vB = alpha~_255 pair (fp32) ; M = Macc_f
        } else {
            // ===== BACKWARD u_t = g_t o (E u_{t+1}), t = 510..256.
            // Outputs i0=2l, i1=2l+1; E[k] = bf16x2(exp(trans[i0][k]), exp(trans[i1][k])).
#pragma unroll
            for (int m = 0; m < 16; m++) {
                float4 ra = __ldg((const float4*)&trans[(2 * lane)     * CRF_L + 4 * m]);
                float4 rb = __ldg((const float4*)&trans[(2 * lane + 1) * CRF_L + 4 * m]);
                E[4 * m + 0] = f2bf2(__expf(ra.x), __expf(rb.x));
                E[4 * m + 1] = f2bf2(__expf(ra.y), __expf(rb.y));
                E[4 * m + 2] = f2bf2(__expf(ra.z), __expf(rb.z));
                E[4 * m + 3] = f2bf2(__expf(ra.w), __expf(rb.w));
            }
            float2 e0 = yp2[511 * 32 + lane];
            vA = __expf(e0.x); vB = __expf(e0.y);   // u_511 = g_511
            ((uint2*)qb[row][1])[lane] = make_uint2(f2bf2(vA, vA), f2bf2(vB, vB)); // u_511 -> buf 1
            pe[2] = yp2[510 * 32 + lane];
            pe[1] = yp2[509 * 32 + lane];
            pe[0] = yp2[508 * 32 + lane];
            pe[3] = yp2[507 * 32 + lane];
            const float2* pf = yp2 + 506 * 32 + lane;  // next prefetch: t=506
            __syncwarp();

#define BSTEP(t_, OFF, CONSUME) do {                                          \
    float2 _e = pe[(t_) & 3];                                                 \
    pe[(t_) & 3] = pf[-(OFF) * 32];                                           \
    CORE(qb[row][(t_ + 1) & 1], qb[row][(t_) & 1], E, _e.x, _e.y, CONSUME);   \
} while (0)

            BSTEP(510, 0, false); BSTEP(509, 1, false); BSTEP(508, 2, false);
            pf -= 3 * 32;
#pragma unroll 1
            for (int g4 = 0; g4 < 63; g4++) {
                const int tg = 507 - 4 * g4;
                BSTEP(tg - 0, 0, true);
                BSTEP(tg - 1, 1, false);
                BSTEP(tg - 2, 2, false);
                BSTEP(tg - 3, 3, false);
                pf -= 4 * 32;
            }
#undef BSTEP
            // final: beta_255 = E u_256 (renorm, no emission). u_256 in buf 0.
            {
                const uint4* q4 = (const uint4*)qb[row][0];
                uint4 qv0 = q4[0];
                unsigned eb = (qv0.x >> 7) & 0xffu;
                float r = __uint_as_float((254u - eb) << 23);
                M = fmaf((float)((int)eb - 127), 0.69314718056f, M);
                unsigned a0 = 0u, a1 = 0u, a2 = 0u, a3 = 0u;
#pragma unroll
                for (int m = 0; m < 16; m++) {
                    uint4 qv = (m == 0) ? qv0 : q4[m];
                    a0 = bfma2(qv.x, E[4 * m + 0], a0);
                    a1 = bfma2(qv.y, E[4 * m + 1], a1);
                    a2 = bfma2(qv.z, E[4 * m + 2], a2);
                    a3 = bfma2(qv.w, E[4 * m + 3], a3);
                }
                float oA = ((bf_lo(a0) + bf_lo(a1)) + (bf_lo(a2) + bf_lo(a3))) * r;
                float oB = ((bf_hi(a0) + bf_hi(a1)) + (bf_hi(a2) + bf_hi(a3))) * r;
                bout2[row][lane] = make_float2(oA, oB);
            }
            if (lane == 0) sMb[row] = M;
        }
    } else {
        // ================= SCORES (wid 4-7) ==============================
        const int sw     = wid - 4;
        const int row    = sw >> 1;
        const int half_t = sw & 1;
        const int b      = 2 * blockIdx.x + row;
        const float* yp = y_pred + (size_t)b * CRF_T * CRF_L;
        const float* yt = y_true + (size_t)b * CRF_T * CRF_L;
        const float4* yp4 = (const float4*)yp;
        const float4* yt4 = (const float4*)yt;
        const int base = half_t * 256;
        const int hh = lane >> 4, l4 = lane & 15;

        float pacc = 0.0f;
#pragma unroll 4
        for (int t = base; t < base + 256; t += 2) {
            const int tt = t + hh;
            float4 p = yp4[tt * 16 + l4];
            float4 q = yt4[tt * 16 + l4];
            pacc += p.x * q.x + p.y * q.y + p.z * q.z + p.w * q.w;
            int c = -1;
            if      (q.x > 0.5f) c = 0;
            else if (q.y > 0.5f) c = 1;
            else if (q.z > 0.5f) c = 2;
            else if (q.w > 0.5f) c = 3;
            unsigned m  = __ballot_sync(0xffffffffu, c >= 0);
            unsigned mh = (m >> (hh * 16)) & 0xffffu;
            int src = hh * 16 + (__ffs(mh) - 1);
            int lab = __shfl_sync(0xffffffffu, 4 * l4 + c, src);
            if (l4 == 0) labs[row][tt] = lab;
        }
        asm volatile("bar.sync 1, 128;" ::: "memory");   // stitch labels

        float ts = 0.0f;
        const int tmax = half_t ? (CRF_T - 1) : 256;
#pragma unroll 4
        for (int t0 = base + lane; t0 < tmax; t0 += 32)
            ts += __ldg(&trans[labs[row][t0] * CRF_L + labs[row][t0 + 1]]);
#pragma unroll
        for (int s = 16; s > 0; s >>= 1) {
            pacc += __shfl_xor_sync(0xffffffffu, pacc, s);
            ts   += __shfl_xor_sync(0xffffffffu, ts, s);
        }
        if (lane == 0) { sP[row][half_t] = pacc; sTs[row][half_t] = ts; }
    }

    __syncthreads();

    // ================= COMBINE: fwd warps (wid 0, 2) =====================
    if (wid < 4 && (wid & 1) == 0) {
        const int row = wid >> 1;
        float2 bb = bout2[row][lane];
        float dot = vA * bb.x + vB * bb.y;
#pragma unroll
        for (int s = 16; s > 0; s >>= 1)
            dot += __shfl_xor_sync(0xffffffffu, dot, s);
        if (lane == 0) {
            float P  = sP[row][0] + sP[row][1];
            float TS = sTs[row][0] + sTs[row][1];
            out[2 * blockIdx.x + row] = (M + sMb[row] + logf(dot)) - P - TS;
        }
    }
#undef CORE
}

extern "C" void kernel_launch(void* const* d_in, const int* in_sizes, int n_in,
                              void* d_out, int out_size) {
    const float* y_true = (const float*)d_in[0];
    const float* y_pred = (const float*)d_in[1];
    const float* trans  = (const float*)d_in[2];
    float* out = (float*)d_out;
    (void)in_sizes; (void)n_in; (void)out_size;
    CRF_48266842472844_kernel<<<CRF_B / 2, 256>>>(y_true, y_pred, trans, out);
}